// round 2
// baseline (speedup 1.0000x reference)
#include <cuda_runtime.h>

#define BATCH       32768
#define NUM_CLASSES 1000
#define FEAT_DIM    128

#define S1_BLOCKS   256
#define S1_THREADS  256          // 8 warps/block -> 2048 warps, 16 rows per warp
#define WARPS_PER_BLOCK (S1_THREADS / 32)
#define TOTAL_WARPS (S1_BLOCKS * WARPS_PER_BLOCK)

__device__ float g_partial[S1_BLOCKS];

__global__ void __launch_bounds__(S1_THREADS)
center_loss_stage1(const float* __restrict__ y,
                   const int* __restrict__ labels,
                   const float* __restrict__ centers)
{
    const int lane   = threadIdx.x & 31;
    const int warpId = threadIdx.x >> 5;
    const int gwarp  = blockIdx.x * WARPS_PER_BLOCK + warpId;

    float acc = 0.0f;

    const float4* __restrict__ y4 = (const float4*)y;
    const float4* __restrict__ c4 = (const float4*)centers;

    for (int row = gwarp; row < BATCH; row += TOTAL_WARPS) {
        int cls = labels[row];                       // int32 (JAX demotes int64)
        cls = min(max(cls, 0), NUM_CLASSES - 1);     // never fault, even if dtype wrong
        float4 yv = y4[row * (FEAT_DIM / 4) + lane];
        float4 cv = c4[cls * (FEAT_DIM / 4) + lane];

        // expansion form to match reference: ||y||^2 + ||c||^2 - 2<y,c>
        float s = yv.x * yv.x + yv.y * yv.y + yv.z * yv.z + yv.w * yv.w
                + cv.x * cv.x + cv.y * cv.y + cv.z * cv.z + cv.w * cv.w
                - 2.0f * (yv.x * cv.x + yv.y * cv.y + yv.z * cv.z + yv.w * cv.w);

        // warp reduce
        #pragma unroll
        for (int off = 16; off > 0; off >>= 1)
            s += __shfl_xor_sync(0xFFFFFFFFu, s, off);

        if (lane == 0)
            acc += fminf(fmaxf(s, 1e-12f), 1e12f);
    }

    // block reduce (deterministic)
    __shared__ float smem[WARPS_PER_BLOCK];
    if (lane == 0) smem[warpId] = acc;
    __syncthreads();

    if (threadIdx.x == 0) {
        float t = 0.0f;
        #pragma unroll
        for (int i = 0; i < WARPS_PER_BLOCK; i++) t += smem[i];
        g_partial[blockIdx.x] = t;
    }
}

__global__ void __launch_bounds__(S1_BLOCKS)
center_loss_stage2(const float* __restrict__ loss_weight, float* __restrict__ out)
{
    __shared__ float smem[S1_BLOCKS];
    smem[threadIdx.x] = g_partial[threadIdx.x];
    __syncthreads();

    // deterministic tree reduce over 256 partials
    for (int off = S1_BLOCKS / 2; off > 0; off >>= 1) {
        if (threadIdx.x < off) smem[threadIdx.x] += smem[threadIdx.x + off];
        __syncthreads();
    }

    if (threadIdx.x == 0) {
        // zeros of the masked matrix are clipped to 1e-12 and summed:
        // B * (C-1) * 1e-12
        float clip_term = (float)((double)BATCH * (double)(NUM_CLASSES - 1) * 1e-12);
        float total = smem[0] + clip_term;
        out[0] = (total / (float)BATCH) * loss_weight[0];
    }
}

extern "C" void kernel_launch(void* const* d_in, const int* in_sizes, int n_in,
                              void* d_out, int out_size)
{
    // Identify inputs by element count (all four are distinct):
    //   y: 32768*128 = 4194304, centers: 1000*128 = 128000,
    //   labels: 32768, loss_weight: 1
    const float* y       = nullptr;
    const int*   labels  = nullptr;
    const float* centers = nullptr;
    const float* lw      = nullptr;

    for (int i = 0; i < n_in; i++) {
        switch (in_sizes[i]) {
            case BATCH * FEAT_DIM:      y       = (const float*)d_in[i]; break;
            case NUM_CLASSES * FEAT_DIM: centers = (const float*)d_in[i]; break;
            case BATCH:                 labels  = (const int*)d_in[i];   break;
            case 1:                     lw      = (const float*)d_in[i]; break;
            default: break;
        }
    }

    float* out = (float*)d_out;

    center_loss_stage1<<<S1_BLOCKS, S1_THREADS>>>(y, labels, centers);
    center_loss_stage2<<<1, S1_BLOCKS>>>(lw, out);
}

// round 3
// speedup vs baseline: 1.4286x; 1.4286x over previous
#include <cuda_runtime.h>

#define BATCH       32768
#define NUM_CLASSES 1000
#define FEAT_DIM    128

#define S1_BLOCKS   1024
#define S1_THREADS  256
#define WARPS_PER_BLOCK (S1_THREADS / 32)            // 8
#define TOTAL_WARPS (S1_BLOCKS * WARPS_PER_BLOCK)    // 8192
#define ROWS_PER_WARP (BATCH / TOTAL_WARPS)          // 4

__device__ float        g_partial[S1_BLOCKS];
__device__ unsigned int g_count = 0;

__global__ void __launch_bounds__(S1_THREADS)
center_loss_fused(const float* __restrict__ y,
                  const int* __restrict__ labels,
                  const float* __restrict__ centers,
                  const float* __restrict__ loss_weight,
                  float* __restrict__ out)
{
    const int lane   = threadIdx.x & 31;
    const int warpId = threadIdx.x >> 5;
    const int gwarp  = blockIdx.x * WARPS_PER_BLOCK + warpId;

    const float4* __restrict__ y4 = (const float4*)y;
    const float4* __restrict__ c4 = (const float4*)centers;

    // ---- per-thread elementwise accumulation (no per-row reduce/clip) ----
    float acc = 0.0f;

    #pragma unroll
    for (int k = 0; k < ROWS_PER_WARP; k++) {
        const int row = gwarp + k * TOTAL_WARPS;
        int cls = labels[row];
        cls = min(max(cls, 0), NUM_CLASSES - 1);
        float4 yv = y4[row * (FEAT_DIM / 4) + lane];
        float4 cv = c4[cls * (FEAT_DIM / 4) + lane];

        acc += yv.x * yv.x + yv.y * yv.y + yv.z * yv.z + yv.w * yv.w;
        acc += cv.x * cv.x + cv.y * cv.y + cv.z * cv.z + cv.w * cv.w;
        acc -= 2.0f * (yv.x * cv.x + yv.y * cv.y + yv.z * cv.z + yv.w * cv.w);
    }

    // ---- warp reduce ----
    #pragma unroll
    for (int off = 16; off > 0; off >>= 1)
        acc += __shfl_xor_sync(0xFFFFFFFFu, acc, off);

    // ---- block reduce ----
    __shared__ float smem[WARPS_PER_BLOCK];
    if (lane == 0) smem[warpId] = acc;
    __syncthreads();

    __shared__ bool isLast;
    if (threadIdx.x == 0) {
        float t = 0.0f;
        #pragma unroll
        for (int i = 0; i < WARPS_PER_BLOCK; i++) t += smem[i];
        g_partial[blockIdx.x] = t;
        __threadfence();
        unsigned int prev = atomicAdd(&g_count, 1u);
        isLast = (prev == (unsigned int)(gridDim.x - 1));
    }
    __syncthreads();

    // ---- last block: deterministic final reduce over 1024 partials ----
    if (isLast) {
        __shared__ float fin[S1_THREADS];
        float t = 0.0f;
        #pragma unroll
        for (int i = 0; i < S1_BLOCKS / S1_THREADS; i++)
            t += g_partial[threadIdx.x + i * S1_THREADS];
        fin[threadIdx.x] = t;
        __syncthreads();

        for (int off = S1_THREADS / 2; off > 0; off >>= 1) {
            if (threadIdx.x < off) fin[threadIdx.x] += fin[threadIdx.x + off];
            __syncthreads();
        }

        if (threadIdx.x == 0) {
            // masked-matrix zeros clip to 1e-12: + B*(C-1)*1e-12, then /B
            float clip_term = (float)((double)BATCH * (double)(NUM_CLASSES - 1) * 1e-12);
            float total = fin[0] + clip_term;
            out[0] = (total / (float)BATCH) * loss_weight[0];
            g_count = 0;  // reset for next graph replay
        }
    }
}

extern "C" void kernel_launch(void* const* d_in, const int* in_sizes, int n_in,
                              void* d_out, int out_size)
{
    // Identify inputs by element count (all distinct):
    //   y: 4194304, centers: 128000, labels: 32768, loss_weight: 1
    const float* y       = nullptr;
    const int*   labels  = nullptr;
    const float* centers = nullptr;
    const float* lw      = nullptr;

    for (int i = 0; i < n_in; i++) {
        switch (in_sizes[i]) {
            case BATCH * FEAT_DIM:       y       = (const float*)d_in[i]; break;
            case NUM_CLASSES * FEAT_DIM: centers = (const float*)d_in[i]; break;
            case BATCH:                  labels  = (const int*)d_in[i];   break;
            case 1:                      lw      = (const float*)d_in[i]; break;
            default: break;
        }
    }

    center_loss_fused<<<S1_BLOCKS, S1_THREADS>>>(y, labels, centers, lw, (float*)d_out);
}